// round 12
// baseline (speedup 1.0000x reference)
#include <cuda_runtime.h>
#include <math.h>

// Problem constants
#define Bsz   4
#define Csz   16
#define Tsz   32
#define Hsz   128
#define Wsz   128
#define Klow  4
#define TAU   0.1
#define EPS2  1e-12f          // (1e-6)^2

#define HW        (Hsz * Wsz)          // 16384
#define HW4       (HW / 4)             // 4096
#define NCOLS     (Bsz * Csz * HW4)    // 262,144 16B-columns
#define BLOCK     256
#define NBLOCKS   740                  // 5 blocks x 148 SMs, all co-resident
#define NTHREADS  (NBLOCKS * BLOCK)    // 189,440

#define N_MAIN  ((double)Bsz * Csz * Tsz * HW)          // 33,554,432
#define N_TEMP  ((double)Bsz * Csz * (Tsz - 1) * HW)    // 32,505,856

// ---------- compile-time DCT tables -> FFMA immediates ----------
__host__ __device__ constexpr double c_reduce(double x) {
    while (x >  3.14159265358979323846) x -= 6.28318530717958647692;
    while (x < -3.14159265358979323846) x += 6.28318530717958647692;
    return x;
}
__host__ __device__ constexpr double c_cos(double x) {
    x = c_reduce(x);
    double x2 = x * x, term = 1.0, sum = 1.0;
    for (int i = 1; i <= 13; i++) {
        term *= -x2 / (double)((2 * i - 1) * (2 * i));
        sum  += term;
    }
    return sum;
}
__host__ __device__ constexpr double c_sqrt(double v) {
    double r = v > 1.0 ? v : 1.0;
    for (int i = 0; i < 64; i++) r = 0.5 * (r + v / r);
    return r;
}
struct Tab {
    float D[Klow][Tsz];
    float G[Klow][Klow];
};
__host__ __device__ constexpr Tab make_tab() {
    Tab r{};
    double Dd[Klow][Tsz] = {};
    const double scale = c_sqrt(2.0 / (double)Tsz);
    for (int n = 0; n < Klow; n++)
        for (int t = 0; t < Tsz; t++) {
            double v = scale * c_cos(3.14159265358979323846 * (2.0 * t + 1.0) * n / (2.0 * Tsz));
            if (n == 0) v *= 0.70710678118654752440;
            Dd[n][t] = v;
            r.D[n][t] = (float)v;
        }
    for (int n = 0; n < Klow; n++)
        for (int m = 0; m < Klow; m++) {
            double g = 0.0;
            for (int s = 0; s < Tsz - 1; s++)
                g += (Dd[n][s + 1] - Dd[n][s]) * (Dd[m][s + 1] - Dd[m][s]);
            r.G[n][m] = (float)g;
        }
    return r;
}

// ---------- global scratch ----------
__device__ float g_partials[2 * NBLOCKS];
__device__ unsigned int g_count = 0;   // last block resets -> graph-replay safe

// Single-MUFU sqrt (harness has no -use_fast_math; sqrtf would emit a ~15-instr
// correctly-rounded emulation sequence).
__device__ __forceinline__ float sqrt_approx(float x) {
    float r;
    asm("sqrt.approx.f32 %0, %1;" : "=f"(r) : "f"(x));
    return r;
}

__global__ void __launch_bounds__(BLOCK, 5)
loss_fused(const float4* __restrict__ X, const float4* __restrict__ Y,
           float* __restrict__ out)
{
    constexpr Tab TAB = make_tab();   // compile-time; all uses unroll-constant

    __shared__ float red[2][BLOCK];
    __shared__ bool  is_last;

    const int tid = threadIdx.x;
    const unsigned gthread = blockIdx.x * BLOCK + tid;

    float ch0 = 0.f, ch1 = 0.f, ch2 = 0.f, ch3 = 0.f;
    float temp = 0.0f;

    // Grid-stride over columns. CRITICAL: unroll 1 — merging iterations lets
    // ptxas front-batch 100+ loads and spill (R6: +229 MB DRAM traffic).
    #pragma unroll 1
    for (unsigned colidx = gthread; colidx < NCOLS; colidx += NTHREADS) {
        const unsigned hw4 = colidx & (HW4 - 1);
        const unsigned bc  = colidx >> 12;
        const size_t base  = (size_t)bc * (Tsz * HW4) + hw4;
        const float4* __restrict__ px = X + base;
        const float4* __restrict__ py = Y + base;

        float c[Klow][4];               // [dct row][lane]
        #pragma unroll
        for (int n = 0; n < Klow; n++)
            #pragma unroll
            for (int l = 0; l < 4; l++) c[n][l] = 0.0f;

        // 4-timestep staging: 8 independent LDG.128 issued before any use.
        #pragma unroll
        for (int tt = 0; tt < Tsz; tt += 4) {
            float4 a[4], b[4];
            #pragma unroll
            for (int j = 0; j < 4; j++) {
                a[j] = __ldcs(&px[(tt + j) * HW4]);
                b[j] = __ldcs(&py[(tt + j) * HW4]);
            }
            #pragma unroll
            for (int j = 0; j < 4; j++) {
                float d0 = a[j].x - b[j].x;
                float d1 = a[j].y - b[j].y;
                float d2 = a[j].z - b[j].z;
                float d3 = a[j].w - b[j].w;

                ch0 += sqrt_approx(fmaf(d0, d0, EPS2));
                ch1 += sqrt_approx(fmaf(d1, d1, EPS2));
                ch2 += sqrt_approx(fmaf(d2, d2, EPS2));
                ch3 += sqrt_approx(fmaf(d3, d3, EPS2));

                // Weights fold to FFMA immediates (t = tt+j unroll-constant)
                #pragma unroll
                for (int n = 0; n < Klow; n++) {
                    const float w = TAB.D[n][tt + j];
                    c[n][0] = fmaf(d0, w, c[n][0]);
                    c[n][1] = fmaf(d1, w, c[n][1]);
                    c[n][2] = fmaf(d2, w, c[n][2]);
                    c[n][3] = fmaf(d3, w, c[n][3]);
                }
            }
        }

        // temp += sum over 4 lanes of c^T G c  (G as immediates)
        #pragma unroll
        for (int l = 0; l < 4; l++) {
            #pragma unroll
            for (int n = 0; n < Klow; n++) {
                float acc = 0.0f;
                #pragma unroll
                for (int m = 0; m < Klow; m++)
                    acc = fmaf(c[m][l], TAB.G[n][m], acc);
                temp = fmaf(c[n][l], acc, temp);
            }
        }
    }
    float charb = (ch0 + ch1) + (ch2 + ch3);

    // Deterministic block reduction
    red[0][tid] = charb;
    red[1][tid] = temp;
    __syncthreads();
    for (int s = BLOCK / 2; s > 0; s >>= 1) {
        if (tid < s) {
            red[0][tid] += red[0][tid + s];
            red[1][tid] += red[1][tid + s];
        }
        __syncthreads();
    }

    if (tid == 0) {
        g_partials[blockIdx.x]           = red[0][0];
        g_partials[NBLOCKS + blockIdx.x] = red[1][0];
        __threadfence();
        unsigned int ticket = atomicAdd(&g_count, 1u);
        is_last = (ticket == NBLOCKS - 1);
    }
    __syncthreads();

    // Last block: deterministic final reduction in double
    if (is_last) {
        __shared__ double r0[BLOCK];
        __shared__ double r1[BLOCK];
        double s0 = 0.0, s1 = 0.0;
        #pragma unroll 3
        for (int k = tid; k < NBLOCKS; k += BLOCK) {
            s0 += (double)__ldcg(&g_partials[k]);
            s1 += (double)__ldcg(&g_partials[NBLOCKS + k]);
        }
        r0[tid] = s0;
        r1[tid] = s1;
        __syncthreads();
        for (int s = BLOCK / 2; s > 0; s >>= 1) {
            if (tid < s) {
                r0[tid] += r0[tid + s];
                r1[tid] += r1[tid + s];
            }
            __syncthreads();
        }
        if (tid == 0) {
            double L_main = r0[0] / N_MAIN;
            double L_temp = r1[0] / N_TEMP;
            double total  = L_main + TAU * L_temp;
            out[0] = (float)total;
            out[1] = (float)L_main;
            out[2] = (float)L_temp;
            g_count = 0;   // reset for next graph replay
        }
    }
}

extern "C" void kernel_launch(void* const* d_in, const int* in_sizes, int n_in,
                              void* d_out, int out_size)
{
    const float4* X = (const float4*)d_in[0];
    const float4* Y = (const float4*)d_in[1];
    float* out = (float*)d_out;

    loss_fused<<<NBLOCKS, BLOCK>>>(X, Y, out);
}

// round 13
// speedup vs baseline: 1.0435x; 1.0435x over previous
#include <cuda_runtime.h>
#include <math.h>

// Problem constants
#define Bsz   4
#define Csz   16
#define Tsz   32
#define Hsz   128
#define Wsz   128
#define Klow  4
#define TAU   0.1
#define EPS2  1e-12f          // (1e-6)^2

#define HW        (Hsz * Wsz)          // 16384
#define HW4       (HW / 4)             // 4096
#define NCOLS     (Bsz * Csz * HW4)    // 262,144 16B-columns
#define BLOCK     128                  // smaller tile: per-SM block count 7 vs 6 (1.2% imbalance)
#define NBLOCKS   1024                 // all co-resident (cap ~10/SM at 50 regs)
#define NTHREADS  (NBLOCKS * BLOCK)    // 131,072 — identical to R11 concurrency
#define COLS_PER_THREAD 2

#define N_MAIN  ((double)Bsz * Csz * Tsz * HW)          // 33,554,432
#define N_TEMP  ((double)Bsz * Csz * (Tsz - 1) * HW)    // 32,505,856

// ---------- compile-time DCT tables -> FFMA immediates ----------
__host__ __device__ constexpr double c_reduce(double x) {
    while (x >  3.14159265358979323846) x -= 6.28318530717958647692;
    while (x < -3.14159265358979323846) x += 6.28318530717958647692;
    return x;
}
__host__ __device__ constexpr double c_cos(double x) {
    x = c_reduce(x);
    double x2 = x * x, term = 1.0, sum = 1.0;
    for (int i = 1; i <= 13; i++) {
        term *= -x2 / (double)((2 * i - 1) * (2 * i));
        sum  += term;
    }
    return sum;
}
__host__ __device__ constexpr double c_sqrt(double v) {
    double r = v > 1.0 ? v : 1.0;
    for (int i = 0; i < 64; i++) r = 0.5 * (r + v / r);
    return r;
}
struct Tab {
    float D[Klow][Tsz];
    float G[Klow][Klow];
};
__host__ __device__ constexpr Tab make_tab() {
    Tab r{};
    double Dd[Klow][Tsz] = {};
    const double scale = c_sqrt(2.0 / (double)Tsz);
    for (int n = 0; n < Klow; n++)
        for (int t = 0; t < Tsz; t++) {
            double v = scale * c_cos(3.14159265358979323846 * (2.0 * t + 1.0) * n / (2.0 * Tsz));
            if (n == 0) v *= 0.70710678118654752440;
            Dd[n][t] = v;
            r.D[n][t] = (float)v;
        }
    for (int n = 0; n < Klow; n++)
        for (int m = 0; m < Klow; m++) {
            double g = 0.0;
            for (int s = 0; s < Tsz - 1; s++)
                g += (Dd[n][s + 1] - Dd[n][s]) * (Dd[m][s + 1] - Dd[m][s]);
            r.G[n][m] = (float)g;
        }
    return r;
}

// ---------- global scratch ----------
__device__ float g_partials[2 * NBLOCKS];
__device__ unsigned int g_count = 0;   // last block resets -> graph-replay safe

// Single-MUFU sqrt (harness has no -use_fast_math; sqrtf would emit a ~15-instr
// correctly-rounded emulation sequence).
__device__ __forceinline__ float sqrt_approx(float x) {
    float r;
    asm("sqrt.approx.f32 %0, %1;" : "=f"(r) : "f"(x));
    return r;
}

__global__ void __launch_bounds__(BLOCK)
loss_fused(const float4* __restrict__ X, const float4* __restrict__ Y,
           float* __restrict__ out)
{
    constexpr Tab TAB = make_tab();   // compile-time; all uses unroll-constant

    __shared__ float red[2][BLOCK];
    __shared__ bool  is_last;

    const int tid = threadIdx.x;

    // Thread handles columns i and i + NTHREADS (same hw4, bc offset +32).
    const unsigned i   = blockIdx.x * BLOCK + tid;
    const unsigned hw4 = i & (HW4 - 1);
    const unsigned bc  = i >> 12;               // 0..31; second col is bc+32
    const size_t base0 = (size_t)bc * (Tsz * HW4) + hw4;

    float ch0 = 0.f, ch1 = 0.f, ch2 = 0.f, ch3 = 0.f;
    float temp = 0.0f;

    // CRITICAL: unroll 1 — merging both columns' 128 loads into one straight
    // line makes ptxas spill (R6: +229 MB DRAM traffic).
    #pragma unroll 1
    for (int colit = 0; colit < COLS_PER_THREAD; colit++) {
        const size_t base = base0 + (size_t)colit * 32 * (Tsz * HW4);
        const float4* __restrict__ px = X + base;
        const float4* __restrict__ py = Y + base;

        float c[Klow][4];               // [dct row][lane]
        #pragma unroll
        for (int n = 0; n < Klow; n++)
            #pragma unroll
            for (int l = 0; l < 4; l++) c[n][l] = 0.0f;

        // 4-timestep staging: 8 independent LDG.128 issued before any use.
        #pragma unroll
        for (int tt = 0; tt < Tsz; tt += 4) {
            float4 a[4], b[4];
            #pragma unroll
            for (int j = 0; j < 4; j++) {
                a[j] = __ldcs(&px[(tt + j) * HW4]);
                b[j] = __ldcs(&py[(tt + j) * HW4]);
            }
            #pragma unroll
            for (int j = 0; j < 4; j++) {
                float d0 = a[j].x - b[j].x;
                float d1 = a[j].y - b[j].y;
                float d2 = a[j].z - b[j].z;
                float d3 = a[j].w - b[j].w;

                ch0 += sqrt_approx(fmaf(d0, d0, EPS2));
                ch1 += sqrt_approx(fmaf(d1, d1, EPS2));
                ch2 += sqrt_approx(fmaf(d2, d2, EPS2));
                ch3 += sqrt_approx(fmaf(d3, d3, EPS2));

                // Weights fold to FFMA immediates (t = tt+j unroll-constant)
                #pragma unroll
                for (int n = 0; n < Klow; n++) {
                    const float w = TAB.D[n][tt + j];
                    c[n][0] = fmaf(d0, w, c[n][0]);
                    c[n][1] = fmaf(d1, w, c[n][1]);
                    c[n][2] = fmaf(d2, w, c[n][2]);
                    c[n][3] = fmaf(d3, w, c[n][3]);
                }
            }
        }

        // temp += sum over 4 lanes of c^T G c  (G as immediates)
        #pragma unroll
        for (int l = 0; l < 4; l++) {
            #pragma unroll
            for (int n = 0; n < Klow; n++) {
                float acc = 0.0f;
                #pragma unroll
                for (int m = 0; m < Klow; m++)
                    acc = fmaf(c[m][l], TAB.G[n][m], acc);
                temp = fmaf(c[n][l], acc, temp);
            }
        }
    }
    float charb = (ch0 + ch1) + (ch2 + ch3);

    // Deterministic block reduction
    red[0][tid] = charb;
    red[1][tid] = temp;
    __syncthreads();
    for (int s = BLOCK / 2; s > 0; s >>= 1) {
        if (tid < s) {
            red[0][tid] += red[0][tid + s];
            red[1][tid] += red[1][tid + s];
        }
        __syncthreads();
    }

    if (tid == 0) {
        g_partials[blockIdx.x]           = red[0][0];
        g_partials[NBLOCKS + blockIdx.x] = red[1][0];
        __threadfence();
        unsigned int ticket = atomicAdd(&g_count, 1u);
        is_last = (ticket == NBLOCKS - 1);
    }
    __syncthreads();

    // Last block: deterministic final reduction in double
    if (is_last) {
        __shared__ double r0[BLOCK];
        __shared__ double r1[BLOCK];
        double s0 = 0.0, s1 = 0.0;
        #pragma unroll 8
        for (int k = tid; k < NBLOCKS; k += BLOCK) {
            s0 += (double)__ldcg(&g_partials[k]);
            s1 += (double)__ldcg(&g_partials[NBLOCKS + k]);
        }
        r0[tid] = s0;
        r1[tid] = s1;
        __syncthreads();
        for (int s = BLOCK / 2; s > 0; s >>= 1) {
            if (tid < s) {
                r0[tid] += r0[tid + s];
                r1[tid] += r1[tid + s];
            }
            __syncthreads();
        }
        if (tid == 0) {
            double L_main = r0[0] / N_MAIN;
            double L_temp = r1[0] / N_TEMP;
            double total  = L_main + TAU * L_temp;
            out[0] = (float)total;
            out[1] = (float)L_main;
            out[2] = (float)L_temp;
            g_count = 0;   // reset for next graph replay
        }
    }
}

extern "C" void kernel_launch(void* const* d_in, const int* in_sizes, int n_in,
                              void* d_out, int out_size)
{
    const float4* X = (const float4*)d_in[0];
    const float4* Y = (const float4*)d_in[1];
    float* out = (float*)d_out;

    loss_fused<<<NBLOCKS, BLOCK>>>(X, Y, out);
}

// round 14
// speedup vs baseline: 1.0576x; 1.0136x over previous
#include <cuda_runtime.h>
#include <math.h>

// Problem constants
#define Bsz   4
#define Csz   16
#define Tsz   32
#define Hsz   128
#define Wsz   128
#define Klow  4
#define TAU   0.1
#define EPS2  1e-12f          // (1e-6)^2

#define HW        (Hsz * Wsz)          // 16384
#define HW4       (HW / 4)             // 4096
#define NCOLS     (Bsz * Csz * HW4)    // 262,144 16B-columns
#define BLOCK     128                  // R13: per-SM block count 7 vs 6 (1.2% imbalance)
#define NWARPS    (BLOCK / 32)
#define NBLOCKS   1024                 // all co-resident, ~28 warps/SM (measured optimum)
#define NTHREADS  (NBLOCKS * BLOCK)    // 131,072
#define COLS_PER_THREAD 2

#define N_MAIN  ((double)Bsz * Csz * Tsz * HW)          // 33,554,432
#define N_TEMP  ((double)Bsz * Csz * (Tsz - 1) * HW)    // 32,505,856

// ---------- compile-time DCT tables -> FFMA immediates ----------
__host__ __device__ constexpr double c_reduce(double x) {
    while (x >  3.14159265358979323846) x -= 6.28318530717958647692;
    while (x < -3.14159265358979323846) x += 6.28318530717958647692;
    return x;
}
__host__ __device__ constexpr double c_cos(double x) {
    x = c_reduce(x);
    double x2 = x * x, term = 1.0, sum = 1.0;
    for (int i = 1; i <= 13; i++) {
        term *= -x2 / (double)((2 * i - 1) * (2 * i));
        sum  += term;
    }
    return sum;
}
__host__ __device__ constexpr double c_sqrt(double v) {
    double r = v > 1.0 ? v : 1.0;
    for (int i = 0; i < 64; i++) r = 0.5 * (r + v / r);
    return r;
}
struct Tab {
    float D[Klow][Tsz];
    float G[Klow][Klow];
};
__host__ __device__ constexpr Tab make_tab() {
    Tab r{};
    double Dd[Klow][Tsz] = {};
    const double scale = c_sqrt(2.0 / (double)Tsz);
    for (int n = 0; n < Klow; n++)
        for (int t = 0; t < Tsz; t++) {
            double v = scale * c_cos(3.14159265358979323846 * (2.0 * t + 1.0) * n / (2.0 * Tsz));
            if (n == 0) v *= 0.70710678118654752440;
            Dd[n][t] = v;
            r.D[n][t] = (float)v;
        }
    for (int n = 0; n < Klow; n++)
        for (int m = 0; m < Klow; m++) {
            double g = 0.0;
            for (int s = 0; s < Tsz - 1; s++)
                g += (Dd[n][s + 1] - Dd[n][s]) * (Dd[m][s + 1] - Dd[m][s]);
            r.G[n][m] = (float)g;
        }
    return r;
}

// ---------- global scratch ----------
// charb partials in [0, NBLOCKS), temp partials in [NBLOCKS, 2*NBLOCKS); 16B aligned
__device__ __align__(16) float g_partials[2 * NBLOCKS];
__device__ unsigned int g_count = 0;   // last block resets -> graph-replay safe

// Single-MUFU sqrt (harness has no -use_fast_math; sqrtf would emit a ~15-instr
// correctly-rounded emulation sequence).
__device__ __forceinline__ float sqrt_approx(float x) {
    float r;
    asm("sqrt.approx.f32 %0, %1;" : "=f"(r) : "f"(x));
    return r;
}

__global__ void __launch_bounds__(BLOCK)
loss_fused(const float4* __restrict__ X, const float4* __restrict__ Y,
           float* __restrict__ out)
{
    constexpr Tab TAB = make_tab();   // compile-time; all uses unroll-constant

    __shared__ float  wsum[2][NWARPS];
    __shared__ double dsum[2][NWARPS];
    __shared__ bool   is_last;

    const int tid  = threadIdx.x;
    const int lane = tid & 31;
    const int wid  = tid >> 5;

    // Thread handles columns i and i + NTHREADS (same hw4, bc offset +32).
    const unsigned i   = blockIdx.x * BLOCK + tid;
    const unsigned hw4 = i & (HW4 - 1);
    const unsigned bc  = i >> 12;               // 0..31; second col is bc+32
    const size_t base0 = (size_t)bc * (Tsz * HW4) + hw4;

    float ch0 = 0.f, ch1 = 0.f, ch2 = 0.f, ch3 = 0.f;
    float temp = 0.0f;

    // CRITICAL: unroll 1 — merging both columns' 128 loads into one straight
    // line makes ptxas spill (R6: +229 MB DRAM traffic).
    #pragma unroll 1
    for (int colit = 0; colit < COLS_PER_THREAD; colit++) {
        const size_t base = base0 + (size_t)colit * 32 * (Tsz * HW4);
        const float4* __restrict__ px = X + base;
        const float4* __restrict__ py = Y + base;

        float c[Klow][4];               // [dct row][lane]
        #pragma unroll
        for (int n = 0; n < Klow; n++)
            #pragma unroll
            for (int l = 0; l < 4; l++) c[n][l] = 0.0f;

        // 4-timestep staging: 8 independent LDG.128 issued before any use.
        #pragma unroll
        for (int tt = 0; tt < Tsz; tt += 4) {
            float4 a[4], b[4];
            #pragma unroll
            for (int j = 0; j < 4; j++) {
                a[j] = __ldcs(&px[(tt + j) * HW4]);
                b[j] = __ldcs(&py[(tt + j) * HW4]);
            }
            #pragma unroll
            for (int j = 0; j < 4; j++) {
                float d0 = a[j].x - b[j].x;
                float d1 = a[j].y - b[j].y;
                float d2 = a[j].z - b[j].z;
                float d3 = a[j].w - b[j].w;

                ch0 += sqrt_approx(fmaf(d0, d0, EPS2));
                ch1 += sqrt_approx(fmaf(d1, d1, EPS2));
                ch2 += sqrt_approx(fmaf(d2, d2, EPS2));
                ch3 += sqrt_approx(fmaf(d3, d3, EPS2));

                // Weights fold to FFMA immediates (t = tt+j unroll-constant)
                #pragma unroll
                for (int n = 0; n < Klow; n++) {
                    const float w = TAB.D[n][tt + j];
                    c[n][0] = fmaf(d0, w, c[n][0]);
                    c[n][1] = fmaf(d1, w, c[n][1]);
                    c[n][2] = fmaf(d2, w, c[n][2]);
                    c[n][3] = fmaf(d3, w, c[n][3]);
                }
            }
        }

        // temp += sum over 4 lanes of c^T G c  (G as immediates)
        #pragma unroll
        for (int l = 0; l < 4; l++) {
            #pragma unroll
            for (int n = 0; n < Klow; n++) {
                float acc = 0.0f;
                #pragma unroll
                for (int m = 0; m < Klow; m++)
                    acc = fmaf(c[m][l], TAB.G[n][m], acc);
                temp = fmaf(c[n][l], acc, temp);
            }
        }
    }
    float charb = (ch0 + ch1) + (ch2 + ch3);

    // Deterministic warp reduction (fixed butterfly order -> replay-stable)
    #pragma unroll
    for (int off = 16; off > 0; off >>= 1) {
        charb += __shfl_xor_sync(0xffffffffu, charb, off);
        temp  += __shfl_xor_sync(0xffffffffu, temp,  off);
    }
    if (lane == 0) { wsum[0][wid] = charb; wsum[1][wid] = temp; }
    __syncthreads();

    if (tid == 0) {
        float cb = (wsum[0][0] + wsum[0][1]) + (wsum[0][2] + wsum[0][3]);
        float tp = (wsum[1][0] + wsum[1][1]) + (wsum[1][2] + wsum[1][3]);
        g_partials[blockIdx.x]           = cb;
        g_partials[NBLOCKS + blockIdx.x] = tp;
        __threadfence();
        unsigned int ticket = atomicAdd(&g_count, 1u);
        is_last = (ticket == NBLOCKS - 1);
    }
    __syncthreads();

    // Last block: deterministic final reduction in double (float4 partial loads)
    if (is_last) {
        const float4* p0 = (const float4*)&g_partials[0];        // 256 float4
        const float4* p1 = (const float4*)&g_partials[NBLOCKS];  // 256 float4
        double s0 = 0.0, s1 = 0.0;
        #pragma unroll
        for (int k = 0; k < (NBLOCKS / 4) / BLOCK; k++) {        // 2 iterations
            float4 v0 = __ldcg(&p0[k * BLOCK + tid]);
            float4 v1 = __ldcg(&p1[k * BLOCK + tid]);
            s0 += ((double)v0.x + (double)v0.y) + ((double)v0.z + (double)v0.w);
            s1 += ((double)v1.x + (double)v1.y) + ((double)v1.z + (double)v1.w);
        }
        #pragma unroll
        for (int off = 16; off > 0; off >>= 1) {
            s0 += __shfl_xor_sync(0xffffffffu, s0, off);
            s1 += __shfl_xor_sync(0xffffffffu, s1, off);
        }
        if (lane == 0) { dsum[0][wid] = s0; dsum[1][wid] = s1; }
        __syncthreads();
        if (tid == 0) {
            double r0 = (dsum[0][0] + dsum[0][1]) + (dsum[0][2] + dsum[0][3]);
            double r1 = (dsum[1][0] + dsum[1][1]) + (dsum[1][2] + dsum[1][3]);
            double L_main = r0 / N_MAIN;
            double L_temp = r1 / N_TEMP;
            double total  = L_main + TAU * L_temp;
            out[0] = (float)total;
            out[1] = (float)L_main;
            out[2] = (float)L_temp;
            g_count = 0;   // reset for next graph replay
        }
    }
}

extern "C" void kernel_launch(void* const* d_in, const int* in_sizes, int n_in,
                              void* d_out, int out_size)
{
    const float4* X = (const float4*)d_in[0];
    const float4* Y = (const float4*)d_in[1];
    float* out = (float*)d_out;

    loss_fused<<<NBLOCKS, BLOCK>>>(X, Y, out);
}